// round 1
// baseline (speedup 1.0000x reference)
#include <cuda_runtime.h>

// Problem constants (fixed by the dataset)
#define NN 20000      // nodes
#define EE 320000     // edges
#define DD 256        // embedding dim
#define HH 256        // hidden dim
#define OO 10         // output dim
#define OPAD 12       // padded z row (16B-aligned float4 loads)
#define GG 64         // graphs

// ---------------- scratch (no allocations allowed) ----------------
__device__ float g_v1[HH];                       // emb[0] @ W1
__device__ float g_M[HH * OO];                   // W2 @ fcW
__device__ float g_c0[OO];                       // b2 @ fcW + fcb
__device__ int   g_deg[NN];
__device__ float g_dis[NN];
__device__ float g_sacc[NN];                     // dis[i] + sum dis[src]
__device__ __align__(16) float g_z[NN * OPAD];   // per-node 10-vector (padded)
__device__ float g_acc[GG * OO];
__device__ int   g_cnt[GG];

// ---------------- K1: tiny precompute ----------------
// block 0: v1[h] = sum_d emb[d]*W1[d][h];  c0[o] = sum_k b2[k]*fcW[k][o] + fcb[o]
// blocks 1..10 (o = bid-1): M[h][o] = sum_k W2[h][k]*fcW[k][o]
__global__ void k_pre(const float* __restrict__ emb, const float* __restrict__ W1,
                      const float* __restrict__ W2, const float* __restrict__ b2,
                      const float* __restrict__ fcW, const float* __restrict__ fcb) {
    __shared__ float s[HH];
    int t = threadIdx.x;
    if (blockIdx.x == 0) {
        s[t] = emb[t];
        __syncthreads();
        float acc = 0.f;
        #pragma unroll 8
        for (int d = 0; d < DD; d++) acc = fmaf(s[d], W1[d * HH + t], acc);
        g_v1[t] = acc;
        if (t < OO) {
            float c = fcb[t];
            for (int k = 0; k < HH; k++) c = fmaf(b2[k], fcW[k * OO + t], c);
            g_c0[t] = c;
        }
    } else {
        int o = blockIdx.x - 1;
        s[t] = fcW[t * OO + o];
        __syncthreads();
        float acc = 0.f;
        const float* w2r = W2 + t * HH;
        #pragma unroll 8
        for (int k = 0; k < HH; k++) acc = fmaf(w2r[k], s[k], acc);
        g_M[t * OO + o] = acc;
    }
}

// ---------------- K2: init ----------------
__global__ void k_init() {
    int i = blockIdx.x * blockDim.x + threadIdx.x;
    if (i < NN) g_deg[i] = 1;             // self-loop
    if (i < GG * OO) g_acc[i] = 0.f;
    if (i < GG) g_cnt[i] = 0;
}

// ---------------- K3: degree + per-graph node count ----------------
__global__ void k_count(const int* __restrict__ dst, const int* __restrict__ batch) {
    int i = blockIdx.x * blockDim.x + threadIdx.x;
    if (i < EE) atomicAdd(&g_deg[dst[i]], 1);
    if (i < NN) atomicAdd(&g_cnt[batch[i]], 1);
}

// ---------------- K4: dis = rsqrt(deg); seed sacc with self-loop ----------------
__global__ void k_dis() {
    int i = blockIdx.x * blockDim.x + threadIdx.x;
    if (i < NN) {
        float d = rsqrtf((float)g_deg[i]);
        g_dis[i] = d;
        g_sacc[i] = d;  // self-loop contribution dis[i]
    }
}

// ---------------- K5: sacc[dst] += dis[src] ----------------
__global__ void k_sacc(const int* __restrict__ src, const int* __restrict__ dst) {
    int i = blockIdx.x * blockDim.x + threadIdx.x;
    if (i < EE) atomicAdd(&g_sacc[dst[i]], g_dis[src[i]]);
}

// ---------------- K6: per-node z[i] = relu(s_i*v1 + b1) @ M ----------------
__global__ void k_z(const float* __restrict__ b1) {
    __shared__ float sv1[HH];
    __shared__ float sb1[HH];
    __shared__ float sM[HH * OO];
    int t = threadIdx.x;
    sv1[t] = g_v1[t];
    sb1[t] = b1[t];
    for (int j = t; j < HH * OO; j += blockDim.x) sM[j] = g_M[j];
    __syncthreads();

    int i = blockIdx.x * blockDim.x + t;
    if (i >= NN) return;

    float s = g_dis[i] * g_sacc[i];
    float za[OO];
    #pragma unroll
    for (int o = 0; o < OO; o++) za[o] = 0.f;

    #pragma unroll 4
    for (int h = 0; h < HH; h++) {
        float v = fmaxf(fmaf(s, sv1[h], sb1[h]), 0.f);
        const float* mr = sM + h * OO;
        #pragma unroll
        for (int o = 0; o < OO; o++) za[o] = fmaf(v, mr[o], za[o]);
    }

    float4* zp = (float4*)(g_z + i * OPAD);
    zp[0] = make_float4(za[0], za[1], za[2], za[3]);
    zp[1] = make_float4(za[4], za[5], za[6], za[7]);
    zp[2] = make_float4(za[8], za[9], 0.f, 0.f);
}

// ---------------- K7: edge aggregation into [G,O] via smem atomics ----------------
__global__ void k_edge(const int* __restrict__ src, const int* __restrict__ dst,
                       const int* __restrict__ batch) {
    __shared__ float sa[GG * OO];
    for (int j = threadIdx.x; j < GG * OO; j += blockDim.x) sa[j] = 0.f;
    __syncthreads();

    const int total = EE + NN;  // real edges + self-loops
    for (int idx = blockIdx.x * blockDim.x + threadIdx.x; idx < total;
         idx += gridDim.x * blockDim.x) {
        int s_, d_;
        if (idx < EE) { s_ = src[idx]; d_ = dst[idx]; }
        else          { s_ = d_ = idx - EE; }
        float w = g_dis[s_] * g_dis[d_];
        int g = batch[d_];
        const float4* zp = (const float4*)(g_z + s_ * OPAD);
        float4 a = zp[0], b = zp[1], c = zp[2];
        float* base = sa + g * OO;
        atomicAdd(base + 0, w * a.x);
        atomicAdd(base + 1, w * a.y);
        atomicAdd(base + 2, w * a.z);
        atomicAdd(base + 3, w * a.w);
        atomicAdd(base + 4, w * b.x);
        atomicAdd(base + 5, w * b.y);
        atomicAdd(base + 6, w * b.z);
        atomicAdd(base + 7, w * b.w);
        atomicAdd(base + 8, w * c.x);
        atomicAdd(base + 9, w * c.y);
    }
    __syncthreads();
    for (int j = threadIdx.x; j < GG * OO; j += blockDim.x)
        atomicAdd(&g_acc[j], sa[j]);
}

// ---------------- K8: final: mean + folded biases ----------------
__global__ void k_final(float* __restrict__ out) {
    int i = blockIdx.x * blockDim.x + threadIdx.x;
    if (i < GG * OO) {
        int g = i / OO, o = i % OO;
        out[i] = g_acc[i] / fmaxf((float)g_cnt[g], 1.f) + g_c0[o];
    }
}

extern "C" void kernel_launch(void* const* d_in, const int* in_sizes, int n_in,
                              void* d_out, int out_size) {
    // metadata order: x, edge_index, batch, emb, W1, b1, W2, b2, fcW, fcb
    const int*   edge  = (const int*)d_in[1];
    const int*   src   = edge;
    const int*   dst   = edge + EE;
    const int*   batch = (const int*)d_in[2];
    const float* emb   = (const float*)d_in[3];
    const float* W1    = (const float*)d_in[4];
    const float* b1    = (const float*)d_in[5];
    const float* W2    = (const float*)d_in[6];
    const float* b2    = (const float*)d_in[7];
    const float* fcW   = (const float*)d_in[8];
    const float* fcb   = (const float*)d_in[9];
    float* out = (float*)d_out;

    k_pre  <<<1 + OO, 256>>>(emb, W1, W2, b2, fcW, fcb);
    k_init <<<(NN + 255) / 256, 256>>>();
    k_count<<<(EE + 255) / 256, 256>>>(dst, batch);
    k_dis  <<<(NN + 255) / 256, 256>>>();
    k_sacc <<<(EE + 255) / 256, 256>>>(src, dst);
    k_z    <<<(NN + 255) / 256, 256>>>(b1);
    k_edge <<<592, 256>>>(src, dst, batch);
    k_final<<<(GG * OO + 255) / 256, 256>>>(out);
}

// round 2
// speedup vs baseline: 1.3927x; 1.3927x over previous
#include <cuda_runtime.h>

// Problem constants (fixed by the dataset)
#define NN 20000      // nodes
#define EE 320000     // edges
#define HH 256        // hidden dim (= D)
#define OO 10         // output dim
#define GG 64         // graphs
#define NBLK 120      // < #SMs on any Blackwell datacenter part -> co-resident
#define NTHR 256
#define NTOT (NBLK * NTHR)
#define PREBLK 11     // blocks 0..10 do weight precompute in phase 1

// ---------------- persistent scratch (no allocations allowed) ----------------
// Invariant: g_deg, g_ssum, g_acc, g_cnt are ZERO on kernel entry (zero at
// module load; re-zeroed at the end of every run). g_z/g_v1/g_M/g_c0 are
// fully overwritten each run.
__device__ float g_v1[HH];                         // emb[0] @ W1
__device__ __align__(16) float g_M[HH * 12];       // (W2 @ fcW), rows padded to 12
__device__ float g_c0[OO];                         // b2 @ fcW + fcb
__device__ int   g_deg[NN];                        // edge in-degree (excl self loop)
__device__ float g_ssum[NN];                       // sum of dis[src] over incoming edges
__device__ __align__(16) float g_z[NN * 12];       // per-node 10-vec, padded
__device__ float g_acc[GG * OO];
__device__ int   g_cnt[GG];

// grid barrier state
__device__ int          g_bar_count;
__device__ volatile int g_bar_gen;

__device__ __forceinline__ void grid_sync() {
    __threadfence();          // make this thread's global writes visible
    __syncthreads();
    if (threadIdx.x == 0) {
        int my = g_bar_gen;
        if (atomicAdd(&g_bar_count, 1) == NBLK - 1) {
            g_bar_count = 0;
            __threadfence();
            g_bar_gen = my + 1;
        } else {
            while (g_bar_gen == my) { __nanosleep(64); }
        }
        __threadfence();
    }
    __syncthreads();
}

__global__ void __launch_bounds__(NTHR, 1) gcn_fused(
    const int* __restrict__ src, const int* __restrict__ dst,
    const int* __restrict__ batch,
    const float* __restrict__ emb, const float* __restrict__ W1,
    const float* __restrict__ b1,  const float* __restrict__ W2,
    const float* __restrict__ b2,  const float* __restrict__ fcW,
    const float* __restrict__ fcb, float* __restrict__ out)
{
    __shared__ __align__(16) float sbuf[3584];   // 14 KB, reused across phases
    const int bid = blockIdx.x;
    const int t   = threadIdx.x;
    const int gtid = bid * NTHR + t;

    // ================= Phase 1: weight precompute  ||  deg + graph counts ====
    if (bid == 0) {
        // v1[t] = sum_d emb[d] * W1[d][t];  c0
        sbuf[t] = emb[t];
        __syncthreads();
        float acc = 0.f;
        #pragma unroll 8
        for (int d = 0; d < HH; d++) acc = fmaf(sbuf[d], W1[d * HH + t], acc);
        g_v1[t] = acc;
        if (t < OO) {
            float c = fcb[t];
            for (int k = 0; k < HH; k++) c = fmaf(b2[k], fcW[k * OO + t], c);
            g_c0[t] = c;
        }
    } else if (bid < PREBLK) {
        // column o of M = W2 @ fcW
        const int o = bid - 1;
        sbuf[t] = fcW[t * OO + o];
        __syncthreads();
        const float4* w2r = (const float4*)(W2 + t * HH);
        float acc = 0.f;
        #pragma unroll 8
        for (int k = 0; k < HH / 4; k++) {
            float4 w = w2r[k];
            acc = fmaf(w.x, sbuf[4 * k + 0], acc);
            acc = fmaf(w.y, sbuf[4 * k + 1], acc);
            acc = fmaf(w.z, sbuf[4 * k + 2], acc);
            acc = fmaf(w.w, sbuf[4 * k + 3], acc);
        }
        g_M[t * 12 + o] = acc;
    } else {
        const int lane0 = (bid - PREBLK) * NTHR + t;
        const int stride = (NBLK - PREBLK) * NTHR;
        for (int e = lane0; e < EE; e += stride) atomicAdd(&g_deg[dst[e]], 1);
        for (int i = lane0; i < NN; i += stride) atomicAdd(&g_cnt[batch[i]], 1);
    }
    grid_sync();

    // ================= Phase 2: ssum[dst] += dis[src] ========================
    for (int e = gtid; e < EE; e += NTOT) {
        int s = src[e];
        atomicAdd(&g_ssum[dst[e]], rsqrtf((float)(g_deg[s] + 1)));
    }
    grid_sync();

    // ================= Phase 3: z[i] = relu(s_i*v1 + b1) @ M =================
    // sbuf: [0,256) v1, [256,512) b1, [512,3584) M (padded 12/row)
    sbuf[t]       = g_v1[t];
    sbuf[256 + t] = b1[t];
    for (int j = t; j < HH * 12; j += NTHR) sbuf[512 + j] = g_M[j];
    __syncthreads();

    for (int i = gtid; i < NN; i += NTOT) {
        float dis = rsqrtf((float)(g_deg[i] + 1));
        float s   = dis * (dis + g_ssum[i]);
        float za[OO];
        #pragma unroll
        for (int o = 0; o < OO; o++) za[o] = 0.f;
        #pragma unroll 4
        for (int h = 0; h < HH; h++) {
            float v = fmaxf(fmaf(s, sbuf[h], sbuf[256 + h]), 0.f);
            const float4* mr = (const float4*)(sbuf + 512 + h * 12);
            float4 m0 = mr[0], m1 = mr[1], m2 = mr[2];
            za[0] = fmaf(v, m0.x, za[0]);
            za[1] = fmaf(v, m0.y, za[1]);
            za[2] = fmaf(v, m0.z, za[2]);
            za[3] = fmaf(v, m0.w, za[3]);
            za[4] = fmaf(v, m1.x, za[4]);
            za[5] = fmaf(v, m1.y, za[5]);
            za[6] = fmaf(v, m1.z, za[6]);
            za[7] = fmaf(v, m1.w, za[7]);
            za[8] = fmaf(v, m2.x, za[8]);
            za[9] = fmaf(v, m2.y, za[9]);
        }
        float4* zp = (float4*)(g_z + i * 12);
        zp[0] = make_float4(za[0], za[1], za[2], za[3]);
        zp[1] = make_float4(za[4], za[5], za[6], za[7]);
        zp[2] = make_float4(za[8], za[9], 0.f, 0.f);
    }
    grid_sync();

    // ================= Phase 4: edge aggregation into [G,O] ==================
    // 4 replicated smem accumulators (one per warp group of 4) to cut collisions
    for (int j = t; j < 4 * GG * OO; j += NTHR) sbuf[j] = 0.f;
    __syncthreads();
    {
        float* sa = sbuf + ((t >> 5) & 3) * (GG * OO);
        const int total = EE + NN;   // real edges + self loops
        for (int idx = gtid; idx < total; idx += NTOT) {
            int s, d;
            if (idx < EE) { s = src[idx]; d = dst[idx]; }
            else          { s = idx - EE; d = s; }
            float w = rsqrtf((float)(g_deg[s] + 1)) * rsqrtf((float)(g_deg[d] + 1));
            int g = batch[d];
            const float4* zp = (const float4*)(g_z + s * 12);
            float4 a = zp[0], b = zp[1], c = zp[2];
            float* base = sa + g * OO;
            atomicAdd(base + 0, w * a.x);
            atomicAdd(base + 1, w * a.y);
            atomicAdd(base + 2, w * a.z);
            atomicAdd(base + 3, w * a.w);
            atomicAdd(base + 4, w * b.x);
            atomicAdd(base + 5, w * b.y);
            atomicAdd(base + 6, w * b.z);
            atomicAdd(base + 7, w * b.w);
            atomicAdd(base + 8, w * c.x);
            atomicAdd(base + 9, w * c.y);
        }
    }
    __syncthreads();
    for (int j = t; j < GG * OO; j += NTHR) {
        float v = sbuf[j] + sbuf[640 + j] + sbuf[1280 + j] + sbuf[1920 + j];
        atomicAdd(&g_acc[j], v);
    }
    grid_sync();

    // ================= Phase 5: output + reset state for next run ============
    if (bid == 0) {
        for (int j = t; j < GG * OO; j += NTHR) {
            int g = j / OO, o = j - g * OO;
            out[j] = g_acc[j] / fmaxf((float)g_cnt[g], 1.f) + g_c0[o];
        }
        __syncthreads();
        for (int j = t; j < GG * OO; j += NTHR) g_acc[j] = 0.f;
        if (t < GG) g_cnt[t] = 0;
    }
    for (int i = gtid; i < NN; i += NTOT) {
        g_deg[i]  = 0;
        g_ssum[i] = 0.f;
    }
}

extern "C" void kernel_launch(void* const* d_in, const int* in_sizes, int n_in,
                              void* d_out, int out_size) {
    // metadata order: x, edge_index, batch, emb, W1, b1, W2, b2, fcW, fcb
    const int*   edge  = (const int*)d_in[1];
    const int*   src   = edge;
    const int*   dst   = edge + EE;
    const int*   batch = (const int*)d_in[2];
    const float* emb   = (const float*)d_in[3];
    const float* W1    = (const float*)d_in[4];
    const float* b1    = (const float*)d_in[5];
    const float* W2    = (const float*)d_in[6];
    const float* b2    = (const float*)d_in[7];
    const float* fcW   = (const float*)d_in[8];
    const float* fcb   = (const float*)d_in[9];
    float* out = (float*)d_out;

    gcn_fused<<<NBLK, NTHR>>>(src, dst, batch, emb, W1, b1, W2, b2, fcW, fcb, out);
}